// round 9
// baseline (speedup 1.0000x reference)
#include <cuda_runtime.h>
#include <cuda_bf16.h>
#include <cuda_fp16.h>
#include <stdint.h>

#define NMAX 100000
#define EMAX 1600000
#define D 48
#define D4 12
#define HSTRIDE 64   // halfs per row (48 used, padded to 128 B)
#define HS4 8        // uint4 per row
#define NSTEPS 5
#define NGRAPH 64
#define DEGB 512
#define BN_EPS 1e-5f
#define ASTR 148     // smem A stride (uints) for tf32 GEMM

// ---------------- device scratch ----------------
__device__ int   g_deg[NMAX];
__device__ float g_dinv[NMAX];
__device__ int   g_rowstart[NMAX + 1];
__device__ int   g_wp[NMAX];
__device__ int   g_ecol[EMAX];
__device__ int   g_scanblk[256];
__device__ int   g_scanoff[256];
__device__ int   g_dhist[DEGB];
__device__ int   g_doff[DEGB];
__device__ int   g_perm[NMAX];
__device__ unsigned g_Wt[144 * 48];                    // tf32-converted weights
__device__ __align__(16) float  g_X [NMAX * D];
__device__ __align__(16) float  g_T1[NMAX * D];
__device__ __align__(16) float  g_T2[NMAX * D];
__device__ __align__(16) __half g_Yh [NMAX * HSTRIDE];
__device__ __align__(16) __half g_Y2h[NMAX * HSTRIDE];
__device__ __align__(16) __half g_Th [NMAX * HSTRIDE];
__device__ double g_bnsum[D];
__device__ double g_bnsq[D];
__device__ float g_g[NGRAPH * D];
__device__ int   g_gstart[NGRAPH + 1];

// ---------------- helpers ----------------
__device__ __forceinline__ float4 f4scale(float s, float4 v) {
    return make_float4(s * v.x, s * v.y, s * v.z, s * v.w);
}
__device__ __forceinline__ int idx_get(const void* p, int i, int is64) {
    return is64 ? (int)((const long long*)p)[i] : ((const int*)p)[i];
}
__device__ __forceinline__ int probe64(const void* p, int NN) {
    const long long* q = (const long long*)p;
    long long v0 = q[0], v1 = q[1], v2 = q[2], v3 = q[3];
    return (v0 >= 0 && v0 < NN && v1 >= 0 && v1 < NN && v2 >= 0 && v2 < NN &&
            v3 >= 0 && v3 < NN);
}
__device__ __forceinline__ unsigned f2tf32(float f) {
    unsigned u;
    asm("cvt.rna.tf32.f32 %0, %1;" : "=r"(u) : "f"(f));
    return u;
}
__device__ __forceinline__ void acc8(const uint4 v, float* a) {
    float2 f0 = __half22float2(*(const __half2*)&v.x);
    float2 f1 = __half22float2(*(const __half2*)&v.y);
    float2 f2 = __half22float2(*(const __half2*)&v.z);
    float2 f3 = __half22float2(*(const __half2*)&v.w);
    a[0] += f0.x; a[1] += f0.y; a[2] += f1.x; a[3] += f1.y;
    a[4] += f2.x; a[5] += f2.y; a[6] += f3.x; a[7] += f3.y;
}
__device__ __forceinline__ void max8(const uint4 v, __half2* mx, __half2* mn) {
    mx[0] = __hmax2(mx[0], *(const __half2*)&v.x);
    mx[1] = __hmax2(mx[1], *(const __half2*)&v.y);
    mx[2] = __hmax2(mx[2], *(const __half2*)&v.z);
    mx[3] = __hmax2(mx[3], *(const __half2*)&v.w);
    mn[0] = __hmin2(mn[0], *(const __half2*)&v.x);
    mn[1] = __hmin2(mn[1], *(const __half2*)&v.y);
    mn[2] = __hmin2(mn[2], *(const __half2*)&v.z);
    mn[3] = __hmin2(mn[3], *(const __half2*)&v.w);
}

// ------- pre0: copy X, count deg, gstart, convert W, zero bnsums -----------
__global__ void k_pre0(const float* __restrict__ x, const void* ei,
                       const void* batch, const float* __restrict__ W, int NN,
                       int EE) {
    int gt = blockIdx.x * blockDim.x + threadIdx.x;
    int gs = gridDim.x * blockDim.x;
    int is64 = probe64(ei, NN);

    for (int i = gt; i < NN * D4; i += gs)
        ((float4*)g_X)[i] = ((const float4*)x)[i];
    for (int e = gt; e < EE; e += gs) {
        int r = idx_get(ei, e, is64);
        if ((unsigned)r < (unsigned)NN) atomicAdd(&g_deg[r], 1);
    }
    for (int i = gt; i <= NN; i += gs) {
        int bi = (i < NN) ? idx_get(batch, i, is64) : NGRAPH;
        int bp = (i > 0) ? idx_get(batch, i - 1, is64) : -1;
        if (bi < 0) bi = 0;
        if (bi > NGRAPH) bi = NGRAPH;
        if (bp < -1) bp = -1;
        if (bp > NGRAPH) bp = NGRAPH;
        for (int g = bp + 1; g <= bi; g++) g_gstart[g] = i;
    }
    for (int i = gt; i < 144 * 48; i += gs) g_Wt[i] = f2tf32(W[i]);
    if (gt < D) { g_bnsum[gt] = 0.0; g_bnsq[gt] = 0.0; }
}

// ---------------- prefix scan over deg (+dinv +degree histogram) -----------
__global__ void k_scan1(int NN) {
    __shared__ int sh[1024];
    __shared__ int hist[DEGB];
    int t = threadIdx.x;
    if (t < DEGB) hist[t] = 0;
    int i = blockIdx.x * 1024 + t;
    int v = (i < NN) ? g_deg[i] : 0;
    sh[t] = v;
    __syncthreads();
    for (int off = 1; off < 1024; off <<= 1) {
        int tv = (t >= off) ? sh[t - off] : 0;
        __syncthreads();
        sh[t] += tv;
        __syncthreads();
    }
    if (i < NN) {
        g_rowstart[i] = sh[t] - v;
        g_dinv[i] = (v > 0) ? rsqrtf((float)v) : 0.0f;
        atomicAdd(&hist[v < DEGB ? v : DEGB - 1], 1);
    }
    if (t == 1023) g_scanblk[blockIdx.x] = sh[1023];
    __syncthreads();
    if (t < DEGB && hist[t] > 0) atomicAdd(&g_dhist[t], hist[t]);
}

__global__ void k_scan2(int NB) {
    __shared__ int sh[128];
    int t = threadIdx.x;
    int v = (t < NB) ? g_scanblk[t] : 0;
    sh[t] = v;
    __syncthreads();
    for (int off = 1; off < 128; off <<= 1) {
        int tv = (t >= off) ? sh[t - off] : 0;
        __syncthreads();
        sh[t] += tv;
        __syncthreads();
    }
    g_scanoff[t] = sh[t] - v;
}

// scan3 + prescale (Yh = half(dinv*X)) fused
__global__ void k_scan3(int NN, int EE) {
    int i = blockIdx.x * 1024 + threadIdx.x;
    if (i < NN) {
        int rs = g_rowstart[i] + g_scanoff[blockIdx.x];
        g_rowstart[i] = rs;
        g_wp[i] = rs;
    }
    if (i == 0) g_rowstart[NN] = EE;
    int gs = gridDim.x * 1024;
    for (int v = i; v < NN * D4; v += gs) {
        int row = v / D4, f = v % D4;
        float4 val = f4scale(g_dinv[row], ((const float4*)g_X)[v]);
        __half2 h0 = __floats2half2_rn(val.x, val.y);
        __half2 h1 = __floats2half2_rn(val.z, val.w);
        ((uint2*)g_Yh)[row * 16 + f] =
            make_uint2(*(unsigned*)&h0, *(unsigned*)&h1);
    }
}

// ---------------- degree counting sort ----------------
__global__ void k_dscan() {
    __shared__ int sh[DEGB];
    int t = threadIdx.x;
    int v = g_dhist[t];
    sh[t] = v;
    __syncthreads();
    for (int off = 1; off < DEGB; off <<= 1) {
        int tv = (t >= off) ? sh[t - off] : 0;
        __syncthreads();
        sh[t] += tv;
        __syncthreads();
    }
    g_doff[t] = sh[t] - v;
    g_dhist[t] = 0;
}

__global__ void k_dscatter(int NN) {
    __shared__ int lh[DEGB];
    __shared__ int lbase[DEGB];
    int t = threadIdx.x;
    lh[t] = 0;
    __syncthreads();
    int i = blockIdx.x * 512 + t;
    int d = 0, lr = 0;
    if (i < NN) {
        d = g_deg[i];
        if (d >= DEGB) d = DEGB - 1;
        lr = atomicAdd(&lh[d], 1);
        g_deg[i] = 0;
    }
    __syncthreads();
    if (lh[t] > 0) lbase[t] = atomicAdd(&g_doff[t], lh[t]);
    __syncthreads();
    if (i < NN) g_perm[lbase[d] + lr] = i;
}

__global__ void k_bucket(const void* __restrict__ ei, int EE, int NN) {
    int is64 = probe64(ei, NN);
    for (int e = blockIdx.x * blockDim.x + threadIdx.x; e < EE;
         e += gridDim.x * blockDim.x) {
        int r = idx_get(ei, e, is64);
        int c = idx_get(ei, EE + e, is64);
        if ((unsigned)r < (unsigned)NN && (unsigned)c < (unsigned)NN) {
            int p = atomicAdd(&g_wp[r], 1);
            if ((unsigned)p < (unsigned)EMAX) g_ecol[p] = c;
        }
    }
}

// ---------------- CSR gather kernels: 6 lanes x uint4 per row --------------
// MODE 0: T1 = -dinv*sum(Yh[c]);  Y2h = dinv*T1;  block 0 zeroes BN sums
// MODE 1: T2 = -2*dinv*sum(Y2h[c]) - X
// MODE 2: BN-finalize; fp16 max/min pool; X = a>=0? a*max+c : a*min+c; Yh
template <int MODE>
__global__ __launch_bounds__(384) void k_gather(const float* __restrict__ gamma,
                                                const float* __restrict__ beta,
                                                int NN) {
    __shared__ __align__(16) float sa[48], sc[48];
    int lt = threadIdx.y * 6 + threadIdx.x;
    if (MODE == 0) {
        if (blockIdx.x == 0 && lt < D) { g_bnsum[lt] = 0.0; g_bnsq[lt] = 0.0; }
    }
    if (MODE == 2) {
        if (lt < D) {
            double mean = g_bnsum[lt] / (double)NN;
            double var = g_bnsq[lt] / (double)NN - mean * mean;
            float a = gamma[lt] * rsqrtf((float)var + BN_EPS);
            sa[lt] = a;
            sc[lt] = beta[lt] - (float)mean * a;
        }
        __syncthreads();
    }
    int vrow = blockIdx.x * 64 + threadIdx.y;
    if (vrow >= NN) return;
    int row = g_perm[vrow];
    int x = threadIdx.x;  // 0..5 (8 features each)
    int s = g_rowstart[row];
    int e = g_rowstart[row + 1];
    const uint4* __restrict__ src =
        (MODE == 0) ? (const uint4*)g_Yh
                    : (MODE == 1) ? (const uint4*)g_Y2h : (const uint4*)g_Th;
    const int* __restrict__ ec = g_ecol;

    if (MODE == 2) {
        __half2 NEG = *(__half2*)&(const unsigned&)(unsigned&)*(unsigned[]){0xFC00FC00u};
        __half2 POS;
        {
            unsigned n = 0xFC00FC00u, p = 0x7C007C00u;
            NEG = *(__half2*)&n;
            POS = *(__half2*)&p;
        }
        __half2 mxA[4] = {NEG, NEG, NEG, NEG}, mxB[4] = {NEG, NEG, NEG, NEG};
        __half2 mnA[4] = {POS, POS, POS, POS}, mnB[4] = {POS, POS, POS, POS};
        int i = s;
        for (; i + 4 <= e; i += 4) {
            int c0 = __ldg(ec + i), c1 = __ldg(ec + i + 1);
            int c2 = __ldg(ec + i + 2), c3 = __ldg(ec + i + 3);
            uint4 v0 = __ldg(src + c0 * HS4 + x);
            uint4 v1 = __ldg(src + c1 * HS4 + x);
            uint4 v2 = __ldg(src + c2 * HS4 + x);
            uint4 v3 = __ldg(src + c3 * HS4 + x);
            max8(v0, mxA, mnA);
            max8(v1, mxB, mnB);
            max8(v2, mxA, mnA);
            max8(v3, mxB, mnB);
        }
        for (; i < e; i++) {
            int c = __ldg(ec + i);
            max8(__ldg(src + c * HS4 + x), mxA, mnA);
        }
        float4 av0 = ((const float4*)sa)[x * 2];
        float4 av1 = ((const float4*)sa)[x * 2 + 1];
        float4 cv0 = ((const float4*)sc)[x * 2];
        float4 cv1 = ((const float4*)sc)[x * 2 + 1];
        float mx[8], mn[8];
#pragma unroll
        for (int q = 0; q < 4; q++) {
            float2 fa = __half22float2(__hmax2(mxA[q], mxB[q]));
            float2 fb = __half22float2(__hmin2(mnA[q], mnB[q]));
            mx[q * 2] = fa.x; mx[q * 2 + 1] = fa.y;
            mn[q * 2] = fb.x; mn[q * 2 + 1] = fb.y;
        }
        float av[8] = {av0.x, av0.y, av0.z, av0.w, av1.x, av1.y, av1.z, av1.w};
        float cv[8] = {cv0.x, cv0.y, cv0.z, cv0.w, cv1.x, cv1.y, cv1.z, cv1.w};
        float o[8];
        bool has = (e > s);
#pragma unroll
        for (int q = 0; q < 8; q++) {
            float sel = (av[q] >= 0.f) ? mx[q] : mn[q];
            o[q] = has ? fmaf(av[q], sel, cv[q]) : 0.f;
        }
        ((float4*)g_X)[row * D4 + x * 2] = make_float4(o[0], o[1], o[2], o[3]);
        ((float4*)g_X)[row * D4 + x * 2 + 1] =
            make_float4(o[4], o[5], o[6], o[7]);
        float dr = g_dinv[row];
        __half2 h0 = __floats2half2_rn(dr * o[0], dr * o[1]);
        __half2 h1 = __floats2half2_rn(dr * o[2], dr * o[3]);
        __half2 h2 = __floats2half2_rn(dr * o[4], dr * o[5]);
        __half2 h3 = __floats2half2_rn(dr * o[6], dr * o[7]);
        ((uint4*)g_Yh)[row * HS4 + x] =
            make_uint4(*(unsigned*)&h0, *(unsigned*)&h1, *(unsigned*)&h2,
                       *(unsigned*)&h3);
    } else {
        float aA[8] = {0, 0, 0, 0, 0, 0, 0, 0};
        float aB[8] = {0, 0, 0, 0, 0, 0, 0, 0};
        int i = s;
        for (; i + 4 <= e; i += 4) {
            int c0 = __ldg(ec + i), c1 = __ldg(ec + i + 1);
            int c2 = __ldg(ec + i + 2), c3 = __ldg(ec + i + 3);
            uint4 v0 = __ldg(src + c0 * HS4 + x);
            uint4 v1 = __ldg(src + c1 * HS4 + x);
            uint4 v2 = __ldg(src + c2 * HS4 + x);
            uint4 v3 = __ldg(src + c3 * HS4 + x);
            acc8(v0, aA);
            acc8(v1, aB);
            acc8(v2, aA);
            acc8(v3, aB);
        }
        for (; i < e; i++) {
            int c = __ldg(ec + i);
            acc8(__ldg(src + c * HS4 + x), aA);
        }
        float sum[8];
#pragma unroll
        for (int q = 0; q < 8; q++) sum[q] = aA[q] + aB[q];
        float dr = g_dinv[row];
        if (MODE == 0) {
            float t1[8];
#pragma unroll
            for (int q = 0; q < 8; q++) t1[q] = -dr * sum[q];
            ((float4*)g_T1)[row * D4 + x * 2] =
                make_float4(t1[0], t1[1], t1[2], t1[3]);
            ((float4*)g_T1)[row * D4 + x * 2 + 1] =
                make_float4(t1[4], t1[5], t1[6], t1[7]);
            __half2 h0 = __floats2half2_rn(dr * t1[0], dr * t1[1]);
            __half2 h1 = __floats2half2_rn(dr * t1[2], dr * t1[3]);
            __half2 h2 = __floats2half2_rn(dr * t1[4], dr * t1[5]);
            __half2 h3 = __floats2half2_rn(dr * t1[6], dr * t1[7]);
            ((uint4*)g_Y2h)[row * HS4 + x] =
                make_uint4(*(unsigned*)&h0, *(unsigned*)&h1, *(unsigned*)&h2,
                           *(unsigned*)&h3);
        } else {
            float4 xr0 = __ldg((const float4*)g_X + row * D4 + x * 2);
            float4 xr1 = __ldg((const float4*)g_X + row * D4 + x * 2 + 1);
            float nd = -2.0f * dr;
            ((float4*)g_T2)[row * D4 + x * 2] = make_float4(
                fmaf(nd, sum[0], -xr0.x), fmaf(nd, sum[1], -xr0.y),
                fmaf(nd, sum[2], -xr0.z), fmaf(nd, sum[3], -xr0.w));
            ((float4*)g_T2)[row * D4 + x * 2 + 1] = make_float4(
                fmaf(nd, sum[4], -xr1.x), fmaf(nd, sum[5], -xr1.y),
                fmaf(nd, sum[6], -xr1.z), fmaf(nd, sum[7], -xr1.w));
        }
    }
}

// ------- tf32 tensor-core cheb GEMM + fused BN stats -----------------------
__global__ __launch_bounds__(128) void k_gemm(const float* __restrict__ b,
                                              int NN) {
    __shared__ unsigned As[64 * ASTR];
    __shared__ float bsumS[48], bsqS[48];
    int tid = threadIdx.x;
    int w = tid >> 5;
    int lane = tid & 31;
    int g = lane >> 2;
    int t = lane & 3;
    int nodebase = blockIdx.x * 64;

    if (tid < 48) { bsumS[tid] = 0.f; bsqS[tid] = 0.f; }

    for (int idx = tid; idx < 64 * 36; idx += 128) {
        int node = idx / 36, q = idx % 36;
        int buf = q / 12, c4 = q % 12;
        int gn = nodebase + node;
        float4 v = make_float4(0.f, 0.f, 0.f, 0.f);
        if (gn < NN) {
            const float* sp = (buf == 0) ? g_X : (buf == 1) ? g_T1 : g_T2;
            v = ((const float4*)sp)[gn * D4 + c4];
        }
        int k = buf * 48 + c4 * 4;
        unsigned* dst = &As[node * ASTR + k];
        dst[0] = f2tf32(v.x);
        dst[1] = f2tf32(v.y);
        dst[2] = f2tf32(v.z);
        dst[3] = f2tf32(v.w);
    }
    __syncthreads();

    float acc[6][4];
#pragma unroll
    for (int j = 0; j < 6; j++)
#pragma unroll
        for (int q = 0; q < 4; q++) acc[j][q] = 0.f;

    const unsigned* __restrict__ Wt = g_Wt;
    int r0s = (w * 16 + g) * ASTR;
    int r1s = (w * 16 + g + 8) * ASTR;
#pragma unroll
    for (int s = 0; s < 18; s++) {
        int k0 = s * 8;
        unsigned a0 = As[r0s + k0 + t];
        unsigned a1 = As[r1s + k0 + t];
        unsigned a2 = As[r0s + k0 + t + 4];
        unsigned a3 = As[r1s + k0 + t + 4];
#pragma unroll
        for (int j = 0; j < 6; j++) {
            unsigned b0 = __ldg(&Wt[(k0 + t) * 48 + j * 8 + g]);
            unsigned b1 = __ldg(&Wt[(k0 + t + 4) * 48 + j * 8 + g]);
            asm volatile(
                "mma.sync.aligned.m16n8k8.row.col.f32.tf32.tf32.f32 "
                "{%0,%1,%2,%3}, {%4,%5,%6,%7}, {%8,%9}, {%0,%1,%2,%3};"
                : "+f"(acc[j][0]), "+f"(acc[j][1]), "+f"(acc[j][2]),
                  "+f"(acc[j][3])
                : "r"(a0), "r"(a1), "r"(a2), "r"(a3), "r"(b0), "r"(b1));
        }
    }

    int r0 = nodebase + w * 16 + g;
    int r1 = r0 + 8;
    bool v0 = r0 < NN, v1 = r1 < NN;
#pragma unroll
    for (int j = 0; j < 6; j++) {
        int col0 = j * 8 + 2 * t;
        float bb0 = __ldg(b + col0);
        float bb1 = __ldg(b + col0 + 1);
        float o00 = fmaxf(acc[j][0] + bb0, 0.f);
        float o01 = fmaxf(acc[j][1] + bb1, 0.f);
        float o10 = fmaxf(acc[j][2] + bb0, 0.f);
        float o11 = fmaxf(acc[j][3] + bb1, 0.f);
        if (v0) {
            __half2 h = __floats2half2_rn(o00, o01);
            ((unsigned*)g_Th)[r0 * 32 + j * 4 + t] = *(unsigned*)&h;
        }
        if (v1) {
            __half2 h = __floats2half2_rn(o10, o11);
            ((unsigned*)g_Th)[r1 * 32 + j * 4 + t] = *(unsigned*)&h;
        }
        float s0 = (v0 ? o00 : 0.f) + (v1 ? o10 : 0.f);
        float s1 = (v0 ? o01 : 0.f) + (v1 ? o11 : 0.f);
        float q0 = (v0 ? o00 * o00 : 0.f) + (v1 ? o10 * o10 : 0.f);
        float q1 = (v0 ? o01 * o01 : 0.f) + (v1 ? o11 * o11 : 0.f);
#pragma unroll
        for (int m = 4; m < 32; m <<= 1) {
            s0 += __shfl_xor_sync(0xffffffffu, s0, m);
            s1 += __shfl_xor_sync(0xffffffffu, s1, m);
            q0 += __shfl_xor_sync(0xffffffffu, q0, m);
            q1 += __shfl_xor_sync(0xffffffffu, q1, m);
        }
        if (g == 0) {
            atomicAdd(&bsumS[col0], s0);
            atomicAdd(&bsumS[col0 + 1], s1);
            atomicAdd(&bsqS[col0], q0);
            atomicAdd(&bsqS[col0 + 1], q1);
        }
    }
    __syncthreads();
    if (tid < 48) {
        atomicAdd(&g_bnsum[tid], (double)bsumS[tid]);
        atomicAdd(&g_bnsq[tid], (double)bsqS[tid]);
    }
}

// ---------------- tail: global add pool + MLP, one block per graph ----------
__global__ __launch_bounds__(256) void k_tail(const float* __restrict__ W1,
                                              const float* __restrict__ b1,
                                              const float* __restrict__ W2,
                                              const float* __restrict__ b2,
                                              float* __restrict__ out) {
    __shared__ float sh[5 * D];
    __shared__ float gr[D];
    __shared__ float hs[128];
    int gph = blockIdx.x;
    int t = threadIdx.x;
    int st = g_gstart[gph], en = g_gstart[gph + 1];
    if (t < 240) {
        int f = t % D;
        int s = t / D;
        float acc = 0.0f;
        for (int n = st + s; n < en; n += 5) acc += g_X[n * D + f];
        sh[s * D + f] = acc;
    }
    __syncthreads();
    if (t < D)
        gr[t] = sh[t] + sh[D + t] + sh[2 * D + t] + sh[3 * D + t] + sh[4 * D + t];
    __syncthreads();
    if (t < 128) {
        float a = b1[t];
#pragma unroll
        for (int k = 0; k < D; k++) a = fmaf(gr[k], W1[k * 128 + t], a);
        hs[t] = fmaxf(a, 0.0f);
    }
    __syncthreads();
    if (t < 12) {
        float o = b2[t];
#pragma unroll
        for (int j = 0; j < 128; j++) o = fmaf(hs[j], W2[j * 12 + t], o);
        out[gph * 12 + t] = o;
    }
}

// ---------------- host orchestration ----------------
extern "C" void kernel_launch(void* const* d_in, const int* in_sizes, int n_in,
                              void* d_out, int out_size) {
    const float* x    = (const float*)d_in[0];
    const void* ei    = d_in[1];
    const void* batch = d_in[2];
    int base = 3;
    if (n_in >= 12 && in_sizes[3] < 100) base = 4;
    const float* W     = (const float*)d_in[base + 0];
    const float* b     = (const float*)d_in[base + 1];
    const float* gamma = (const float*)d_in[base + 2];
    const float* beta  = (const float*)d_in[base + 3];
    const float* W1    = (const float*)d_in[base + 4];
    const float* b1    = (const float*)d_in[base + 5];
    const float* W2    = (const float*)d_in[base + 6];
    const float* b2    = (const float*)d_in[base + 7];

    int NN = in_sizes[0] / D;
    int EE = in_sizes[1] / 2;
    if (NN > NMAX) NN = NMAX;
    if (EE > EMAX) EE = EMAX;

    k_pre0<<<2048, 256>>>(x, ei, batch, W, NN, EE);
    int NB = (NN + 1023) / 1024;
    k_scan1<<<NB, 1024>>>(NN);
    k_scan2<<<1, 128>>>(NB);
    k_scan3<<<NB, 1024>>>(NN, EE);
    k_dscan<<<1, DEGB>>>();
    k_dscatter<<<(NN + 511) / 512, 512>>>(NN);
    k_bucket<<<2048, 256>>>(ei, EE, NN);

    dim3 gb(6, 64);
    int ggrid = (NN + 63) / 64;
    int gemm_grid = (NN + 63) / 64;

    for (int it = 0; it < NSTEPS; it++) {
        k_gather<0><<<ggrid, gb>>>(gamma, beta, NN);
        k_gather<1><<<ggrid, gb>>>(gamma, beta, NN);
        k_gemm<<<gemm_grid, 128>>>(b, NN);
        k_gather<2><<<ggrid, gb>>>(gamma, beta, NN);
    }

    k_tail<<<NGRAPH, 256>>>(W1, b1, W2, b2, (float*)d_out);
}

// round 10
// speedup vs baseline: 1.0461x; 1.0461x over previous
#include <cuda_runtime.h>
#include <cuda_bf16.h>
#include <cuda_fp16.h>
#include <stdint.h>

#define NMAX 100000
#define EMAX 1600000
#define D 48
#define D4 12
#define HSTRIDE 64   // halfs per row (48 used, padded to 128 B)
#define HS2 16       // uint2 per row
#define NSTEPS 5
#define NGRAPH 64
#define DEGB 512
#define BN_EPS 1e-5f
#define ASTR 148     // smem A stride (uints) for tf32 GEMM

// ---------------- device scratch ----------------
__device__ int   g_deg[NMAX];
__device__ float g_dinv[NMAX];
__device__ int   g_rowstart[NMAX + 1];
__device__ int   g_wp[NMAX];
__device__ int   g_ecol[EMAX];
__device__ int   g_scanblk[256];
__device__ int   g_scanoff[256];
__device__ int   g_dhist[DEGB];
__device__ int   g_doff[DEGB];
__device__ int   g_perm[NMAX];
__device__ unsigned g_Wt[144 * 48];                    // tf32-converted weights
__device__ __align__(16) float  g_X [NMAX * D];
__device__ __align__(16) float  g_T1[NMAX * D];
__device__ __align__(16) float  g_T2[NMAX * D];
__device__ __align__(16) __half g_Yh [NMAX * HSTRIDE];
__device__ __align__(16) __half g_Y2h[NMAX * HSTRIDE];
__device__ __align__(16) __half g_Th [NMAX * HSTRIDE];
__device__ double g_bnsum[D];
__device__ double g_bnsq[D];
__device__ float g_g[NGRAPH * D];
__device__ int   g_gstart[NGRAPH + 1];

// ---------------- helpers ----------------
__device__ __forceinline__ float4 f4add(float4 a, float4 b) {
    return make_float4(a.x + b.x, a.y + b.y, a.z + b.z, a.w + b.w);
}
__device__ __forceinline__ float4 f4max(float4 a, float4 b) {
    return make_float4(fmaxf(a.x, b.x), fmaxf(a.y, b.y), fmaxf(a.z, b.z),
                       fmaxf(a.w, b.w));
}
__device__ __forceinline__ float4 f4fma(float4 a, float4 v, float4 c) {
    return make_float4(fmaf(a.x, v.x, c.x), fmaf(a.y, v.y, c.y),
                       fmaf(a.z, v.z, c.z), fmaf(a.w, v.w, c.w));
}
__device__ __forceinline__ float4 f4scale(float s, float4 v) {
    return make_float4(s * v.x, s * v.y, s * v.z, s * v.w);
}
__device__ __forceinline__ float4 h4_to_f4(uint2 v) {
    __half2 h0 = *(__half2*)&v.x;
    __half2 h1 = *(__half2*)&v.y;
    float2 f0 = __half22float2(h0);
    float2 f1 = __half22float2(h1);
    return make_float4(f0.x, f0.y, f1.x, f1.y);
}
__device__ __forceinline__ uint2 f4_to_h4(float4 f) {
    __half2 h0 = __floats2half2_rn(f.x, f.y);
    __half2 h1 = __floats2half2_rn(f.z, f.w);
    uint2 r;
    r.x = *(unsigned*)&h0;
    r.y = *(unsigned*)&h1;
    return r;
}
__device__ __forceinline__ int idx_get(const void* p, int i, int is64) {
    return is64 ? (int)((const long long*)p)[i] : ((const int*)p)[i];
}
__device__ __forceinline__ int probe64(const void* p, int NN) {
    const long long* q = (const long long*)p;
    long long v0 = q[0], v1 = q[1], v2 = q[2], v3 = q[3];
    return (v0 >= 0 && v0 < NN && v1 >= 0 && v1 < NN && v2 >= 0 && v2 < NN &&
            v3 >= 0 && v3 < NN);
}
__device__ __forceinline__ unsigned f2tf32(float f) {
    unsigned u;
    asm("cvt.rna.tf32.f32 %0, %1;" : "=r"(u) : "f"(f));
    return u;
}

// ------- pre0: copy X, count deg, gstart, convert W, zero bnsums -----------
__global__ void k_pre0(const float* __restrict__ x, const void* ei,
                       const void* batch, const float* __restrict__ W, int NN,
                       int EE) {
    int gt = blockIdx.x * blockDim.x + threadIdx.x;
    int gs = gridDim.x * blockDim.x;
    int is64 = probe64(ei, NN);

    for (int i = gt; i < NN * D4; i += gs)
        ((float4*)g_X)[i] = ((const float4*)x)[i];
    for (int e = gt; e < EE; e += gs) {
        int r = idx_get(ei, e, is64);
        if ((unsigned)r < (unsigned)NN) atomicAdd(&g_deg[r], 1);
    }
    for (int i = gt; i <= NN; i += gs) {
        int bi = (i < NN) ? idx_get(batch, i, is64) : NGRAPH;
        int bp = (i > 0) ? idx_get(batch, i - 1, is64) : -1;
        if (bi < 0) bi = 0;
        if (bi > NGRAPH) bi = NGRAPH;
        if (bp < -1) bp = -1;
        if (bp > NGRAPH) bp = NGRAPH;
        for (int g = bp + 1; g <= bi; g++) g_gstart[g] = i;
    }
    for (int i = gt; i < 144 * 48; i += gs) g_Wt[i] = f2tf32(W[i]);
    if (gt < D) { g_bnsum[gt] = 0.0; g_bnsq[gt] = 0.0; }
}

// ---------------- prefix scan over deg (+dinv +degree histogram) -----------
__global__ void k_scan1(int NN) {
    __shared__ int sh[1024];
    __shared__ int hist[DEGB];
    int t = threadIdx.x;
    if (t < DEGB) hist[t] = 0;
    int i = blockIdx.x * 1024 + t;
    int v = (i < NN) ? g_deg[i] : 0;
    sh[t] = v;
    __syncthreads();
    for (int off = 1; off < 1024; off <<= 1) {
        int tv = (t >= off) ? sh[t - off] : 0;
        __syncthreads();
        sh[t] += tv;
        __syncthreads();
    }
    if (i < NN) {
        g_rowstart[i] = sh[t] - v;
        g_dinv[i] = (v > 0) ? rsqrtf((float)v) : 0.0f;
        atomicAdd(&hist[v < DEGB ? v : DEGB - 1], 1);
    }
    if (t == 1023) g_scanblk[blockIdx.x] = sh[1023];
    __syncthreads();
    if (t < DEGB && hist[t] > 0) atomicAdd(&g_dhist[t], hist[t]);
}

__global__ void k_scan2(int NB) {
    __shared__ int sh[128];
    int t = threadIdx.x;
    int v = (t < NB) ? g_scanblk[t] : 0;
    sh[t] = v;
    __syncthreads();
    for (int off = 1; off < 128; off <<= 1) {
        int tv = (t >= off) ? sh[t - off] : 0;
        __syncthreads();
        sh[t] += tv;
        __syncthreads();
    }
    g_scanoff[t] = sh[t] - v;
}

// scan3 + prescale (Yh = half(dinv*X)) fused
__global__ void k_scan3(int NN, int EE) {
    int i = blockIdx.x * 1024 + threadIdx.x;
    if (i < NN) {
        int rs = g_rowstart[i] + g_scanoff[blockIdx.x];
        g_rowstart[i] = rs;
        g_wp[i] = rs;
    }
    if (i == 0) g_rowstart[NN] = EE;
    int gs = gridDim.x * 1024;
    for (int v = i; v < NN * D4; v += gs) {
        int row = v / D4, f = v % D4;
        float4 val = f4scale(g_dinv[row], ((const float4*)g_X)[v]);
        ((uint2*)g_Yh)[row * HS2 + f] = f4_to_h4(val);
    }
}

// ---------------- degree counting sort ----------------
__global__ void k_dscan() {
    __shared__ int sh[DEGB];
    int t = threadIdx.x;
    int v = g_dhist[t];
    sh[t] = v;
    __syncthreads();
    for (int off = 1; off < DEGB; off <<= 1) {
        int tv = (t >= off) ? sh[t - off] : 0;
        __syncthreads();
        sh[t] += tv;
        __syncthreads();
    }
    g_doff[t] = sh[t] - v;
    g_dhist[t] = 0;
}

__global__ void k_dscatter(int NN) {
    __shared__ int lh[DEGB];
    __shared__ int lbase[DEGB];
    int t = threadIdx.x;
    lh[t] = 0;
    __syncthreads();
    int i = blockIdx.x * 512 + t;
    int d = 0, lr = 0;
    if (i < NN) {
        d = g_deg[i];
        if (d >= DEGB) d = DEGB - 1;
        lr = atomicAdd(&lh[d], 1);
        g_deg[i] = 0;
    }
    __syncthreads();
    if (lh[t] > 0) lbase[t] = atomicAdd(&g_doff[t], lh[t]);
    __syncthreads();
    if (i < NN) g_perm[lbase[d] + lr] = i;
}

__global__ void k_bucket(const void* __restrict__ ei, int EE, int NN) {
    int is64 = probe64(ei, NN);
    for (int e = blockIdx.x * blockDim.x + threadIdx.x; e < EE;
         e += gridDim.x * blockDim.x) {
        int r = idx_get(ei, e, is64);
        int c = idx_get(ei, EE + e, is64);
        if ((unsigned)r < (unsigned)NN && (unsigned)c < (unsigned)NN) {
            int p = atomicAdd(&g_wp[r], 1);
            if ((unsigned)p < (unsigned)EMAX) g_ecol[p] = c;
        }
    }
}

// ---------------- CSR gather kernels (12 lanes x uint2, unroll 8) ----------
// MODE 0: T1 = -dinv*sum(Yh[c]);  Y2h = dinv*T1;  block 0 zeroes BN sums
// MODE 1: T2 = -2*dinv*sum(Y2h[c]) - X
// MODE 2: inline BN-finalize, then X = deg>0 ? max_c(a*Th[c]+c) : 0; Yh=dinv*X
template <int MODE>
__global__ __launch_bounds__(384) void k_gather(const float* __restrict__ gamma,
                                                const float* __restrict__ beta,
                                                int NN) {
    __shared__ __align__(16) float sa[48], sc[48];
    int lt = threadIdx.y * 12 + threadIdx.x;
    if (MODE == 0) {
        if (blockIdx.x == 0 && lt < D) { g_bnsum[lt] = 0.0; g_bnsq[lt] = 0.0; }
    }
    if (MODE == 2) {
        if (lt < D) {
            double mean = g_bnsum[lt] / (double)NN;
            double var = g_bnsq[lt] / (double)NN - mean * mean;
            float a = gamma[lt] * rsqrtf((float)var + BN_EPS);
            sa[lt] = a;
            sc[lt] = beta[lt] - (float)mean * a;
        }
        __syncthreads();
    }
    int vrow = blockIdx.x * 32 + threadIdx.y;
    if (vrow >= NN) return;
    int row = g_perm[vrow];
    int f = threadIdx.x;  // 0..11
    int s = g_rowstart[row];
    int e = g_rowstart[row + 1];
    const uint2* __restrict__ src =
        (MODE == 0) ? (const uint2*)g_Yh
                    : (MODE == 1) ? (const uint2*)g_Y2h : (const uint2*)g_Th;
    const int* __restrict__ ec = g_ecol;

    if (MODE == 2) {
        float4 av = ((const float4*)sa)[f];
        float4 cv = ((const float4*)sc)[f];
        float NI = __int_as_float(0xff800000);
        float4 m0 = make_float4(NI, NI, NI, NI), m1 = m0, m2 = m0, m3 = m0;
        float4 m4 = m0, m5 = m0, m6 = m0, m7 = m0;
        int i = s;
        for (; i + 8 <= e; i += 8) {
            int c0 = __ldg(ec + i), c1 = __ldg(ec + i + 1);
            int c2 = __ldg(ec + i + 2), c3 = __ldg(ec + i + 3);
            int c4 = __ldg(ec + i + 4), c5 = __ldg(ec + i + 5);
            int c6 = __ldg(ec + i + 6), c7 = __ldg(ec + i + 7);
            float4 v0 = h4_to_f4(__ldg(src + c0 * HS2 + f));
            float4 v1 = h4_to_f4(__ldg(src + c1 * HS2 + f));
            float4 v2 = h4_to_f4(__ldg(src + c2 * HS2 + f));
            float4 v3 = h4_to_f4(__ldg(src + c3 * HS2 + f));
            float4 v4 = h4_to_f4(__ldg(src + c4 * HS2 + f));
            float4 v5 = h4_to_f4(__ldg(src + c5 * HS2 + f));
            float4 v6 = h4_to_f4(__ldg(src + c6 * HS2 + f));
            float4 v7 = h4_to_f4(__ldg(src + c7 * HS2 + f));
            m0 = f4max(m0, f4fma(av, v0, cv));
            m1 = f4max(m1, f4fma(av, v1, cv));
            m2 = f4max(m2, f4fma(av, v2, cv));
            m3 = f4max(m3, f4fma(av, v3, cv));
            m4 = f4max(m4, f4fma(av, v4, cv));
            m5 = f4max(m5, f4fma(av, v5, cv));
            m6 = f4max(m6, f4fma(av, v6, cv));
            m7 = f4max(m7, f4fma(av, v7, cv));
        }
        for (; i < e; i++) {
            int c = __ldg(ec + i);
            m0 = f4max(m0, f4fma(av, h4_to_f4(__ldg(src + c * HS2 + f)), cv));
        }
        float4 m = f4max(f4max(f4max(m0, m1), f4max(m2, m3)),
                         f4max(f4max(m4, m5), f4max(m6, m7)));
        float4 xv = (e > s) ? m : make_float4(0.f, 0.f, 0.f, 0.f);
        ((float4*)g_X)[row * D4 + f] = xv;
        ((uint2*)g_Yh)[row * HS2 + f] = f4_to_h4(f4scale(g_dinv[row], xv));
    } else {
        float4 a0 = make_float4(0.f, 0.f, 0.f, 0.f), a1 = a0, a2 = a0, a3 = a0;
        float4 a4 = a0, a5 = a0, a6 = a0, a7 = a0;
        int i = s;
        for (; i + 8 <= e; i += 8) {
            int c0 = __ldg(ec + i), c1 = __ldg(ec + i + 1);
            int c2 = __ldg(ec + i + 2), c3 = __ldg(ec + i + 3);
            int c4 = __ldg(ec + i + 4), c5 = __ldg(ec + i + 5);
            int c6 = __ldg(ec + i + 6), c7 = __ldg(ec + i + 7);
            a0 = f4add(a0, h4_to_f4(__ldg(src + c0 * HS2 + f)));
            a1 = f4add(a1, h4_to_f4(__ldg(src + c1 * HS2 + f)));
            a2 = f4add(a2, h4_to_f4(__ldg(src + c2 * HS2 + f)));
            a3 = f4add(a3, h4_to_f4(__ldg(src + c3 * HS2 + f)));
            a4 = f4add(a4, h4_to_f4(__ldg(src + c4 * HS2 + f)));
            a5 = f4add(a5, h4_to_f4(__ldg(src + c5 * HS2 + f)));
            a6 = f4add(a6, h4_to_f4(__ldg(src + c6 * HS2 + f)));
            a7 = f4add(a7, h4_to_f4(__ldg(src + c7 * HS2 + f)));
        }
        for (; i < e; i++) {
            int c = __ldg(ec + i);
            a0 = f4add(a0, h4_to_f4(__ldg(src + c * HS2 + f)));
        }
        float4 sum = f4add(f4add(f4add(a0, a1), f4add(a2, a3)),
                           f4add(f4add(a4, a5), f4add(a6, a7)));
        float dr = g_dinv[row];
        if (MODE == 0) {
            float4 t1 = f4scale(-dr, sum);
            ((float4*)g_T1)[row * D4 + f] = t1;
            ((uint2*)g_Y2h)[row * HS2 + f] = f4_to_h4(f4scale(dr, t1));
        } else {
            float4 xr = __ldg((const float4*)g_X + row * D4 + f);
            float4 t2;
            float nd = -2.0f * dr;
            t2.x = fmaf(nd, sum.x, -xr.x);
            t2.y = fmaf(nd, sum.y, -xr.y);
            t2.z = fmaf(nd, sum.z, -xr.z);
            t2.w = fmaf(nd, sum.w, -xr.w);
            ((float4*)g_T2)[row * D4 + f] = t2;
        }
    }
}

// ------- tf32 tensor-core cheb GEMM + fused BN stats -----------------------
__global__ __launch_bounds__(128) void k_gemm(const float* __restrict__ b,
                                              int NN) {
    __shared__ unsigned As[64 * ASTR];
    __shared__ float bsumS[48], bsqS[48];
    int tid = threadIdx.x;
    int w = tid >> 5;
    int lane = tid & 31;
    int g = lane >> 2;
    int t = lane & 3;
    int nodebase = blockIdx.x * 64;

    if (tid < 48) { bsumS[tid] = 0.f; bsqS[tid] = 0.f; }

    for (int idx = tid; idx < 64 * 36; idx += 128) {
        int node = idx / 36, q = idx % 36;
        int buf = q / 12, c4 = q % 12;
        int gn = nodebase + node;
        float4 v = make_float4(0.f, 0.f, 0.f, 0.f);
        if (gn < NN) {
            const float* sp = (buf == 0) ? g_X : (buf == 1) ? g_T1 : g_T2;
            v = ((const float4*)sp)[gn * D4 + c4];
        }
        int k = buf * 48 + c4 * 4;
        unsigned* dst = &As[node * ASTR + k];
        dst[0] = f2tf32(v.x);
        dst[1] = f2tf32(v.y);
        dst[2] = f2tf32(v.z);
        dst[3] = f2tf32(v.w);
    }
    __syncthreads();

    float acc[6][4];
#pragma unroll
    for (int j = 0; j < 6; j++)
#pragma unroll
        for (int q = 0; q < 4; q++) acc[j][q] = 0.f;

    const unsigned* __restrict__ Wt = g_Wt;
    int r0s = (w * 16 + g) * ASTR;
    int r1s = (w * 16 + g + 8) * ASTR;
#pragma unroll
    for (int s = 0; s < 18; s++) {
        int k0 = s * 8;
        unsigned a0 = As[r0s + k0 + t];
        unsigned a1 = As[r1s + k0 + t];
        unsigned a2 = As[r0s + k0 + t + 4];
        unsigned a3 = As[r1s + k0 + t + 4];
#pragma unroll
        for (int j = 0; j < 6; j++) {
            unsigned b0 = __ldg(&Wt[(k0 + t) * 48 + j * 8 + g]);
            unsigned b1 = __ldg(&Wt[(k0 + t + 4) * 48 + j * 8 + g]);
            asm volatile(
                "mma.sync.aligned.m16n8k8.row.col.f32.tf32.tf32.f32 "
                "{%0,%1,%2,%3}, {%4,%5,%6,%7}, {%8,%9}, {%0,%1,%2,%3};"
                : "+f"(acc[j][0]), "+f"(acc[j][1]), "+f"(acc[j][2]),
                  "+f"(acc[j][3])
                : "r"(a0), "r"(a1), "r"(a2), "r"(a3), "r"(b0), "r"(b1));
        }
    }

    int r0 = nodebase + w * 16 + g;
    int r1 = r0 + 8;
    bool v0 = r0 < NN, v1 = r1 < NN;
#pragma unroll
    for (int j = 0; j < 6; j++) {
        int col0 = j * 8 + 2 * t;
        float bb0 = __ldg(b + col0);
        float bb1 = __ldg(b + col0 + 1);
        float o00 = fmaxf(acc[j][0] + bb0, 0.f);
        float o01 = fmaxf(acc[j][1] + bb1, 0.f);
        float o10 = fmaxf(acc[j][2] + bb0, 0.f);
        float o11 = fmaxf(acc[j][3] + bb1, 0.f);
        if (v0) {
            __half2 h = __floats2half2_rn(o00, o01);
            ((unsigned*)g_Th)[r0 * 32 + j * 4 + t] = *(unsigned*)&h;
        }
        if (v1) {
            __half2 h = __floats2half2_rn(o10, o11);
            ((unsigned*)g_Th)[r1 * 32 + j * 4 + t] = *(unsigned*)&h;
        }
        float s0 = (v0 ? o00 : 0.f) + (v1 ? o10 : 0.f);
        float s1 = (v0 ? o01 : 0.f) + (v1 ? o11 : 0.f);
        float q0 = (v0 ? o00 * o00 : 0.f) + (v1 ? o10 * o10 : 0.f);
        float q1 = (v0 ? o01 * o01 : 0.f) + (v1 ? o11 * o11 : 0.f);
#pragma unroll
        for (int m = 4; m < 32; m <<= 1) {
            s0 += __shfl_xor_sync(0xffffffffu, s0, m);
            s1 += __shfl_xor_sync(0xffffffffu, s1, m);
            q0 += __shfl_xor_sync(0xffffffffu, q0, m);
            q1 += __shfl_xor_sync(0xffffffffu, q1, m);
        }
        if (g == 0) {
            atomicAdd(&bsumS[col0], s0);
            atomicAdd(&bsumS[col0 + 1], s1);
            atomicAdd(&bsqS[col0], q0);
            atomicAdd(&bsqS[col0 + 1], q1);
        }
    }
    __syncthreads();
    if (tid < 48) {
        atomicAdd(&g_bnsum[tid], (double)bsumS[tid]);
        atomicAdd(&g_bnsq[tid], (double)bsqS[tid]);
    }
}

// ---------------- tail: global add pool + MLP, one block per graph ----------
__global__ __launch_bounds__(256) void k_tail(const float* __restrict__ W1,
                                              const float* __restrict__ b1,
                                              const float* __restrict__ W2,
                                              const float* __restrict__ b2,
                                              float* __restrict__ out) {
    __shared__ float sh[5 * D];
    __shared__ float gr[D];
    __shared__ float hs[128];
    int gph = blockIdx.x;
    int t = threadIdx.x;
    int st = g_gstart[gph], en = g_gstart[gph + 1];
    if (t < 240) {
        int f = t % D;
        int s = t / D;
        float acc = 0.0f;
        for (int n = st + s; n < en; n += 5) acc += g_X[n * D + f];
        sh[s * D + f] = acc;
    }
    __syncthreads();
    if (t < D)
        gr[t] = sh[t] + sh[D + t] + sh[2 * D + t] + sh[3 * D + t] + sh[4 * D + t];
    __syncthreads();
    if (t < 128) {
        float a = b1[t];
#pragma unroll
        for (int k = 0; k < D; k++) a = fmaf(gr[k], W1[k * 128 + t], a);
        hs[t] = fmaxf(a, 0.0f);
    }
    __syncthreads();
    if (t < 12) {
        float o = b2[t];
#pragma unroll
        for (int j = 0; j < 128; j++) o = fmaf(hs[j], W2[j * 12 + t], o);
        out[gph * 12 + t] = o;
    }
}

// ---------------- host orchestration ----------------
extern "C" void kernel_launch(void* const* d_in, const int* in_sizes, int n_in,
                              void* d_out, int out_size) {
    const float* x    = (const float*)d_in[0];
    const void* ei    = d_in[1];
    const void* batch = d_in[2];
    int base = 3;
    if (n_in >= 12 && in_sizes[3] < 100) base = 4;
    const float* W     = (const float*)d_in[base + 0];
    const float* b     = (const float*)d_in[base + 1];
    const float* gamma = (const float*)d_in[base + 2];
    const float* beta  = (const float*)d_in[base + 3];
    const float* W1    = (const float*)d_in[base + 4];
    const float* b1    = (const float*)d_in[base + 5];
    const float* W2    = (const float*)d_in[base + 6];
    const float* b2    = (const float*)d_in[base + 7];

    int NN = in_sizes[0] / D;
    int EE = in_sizes[1] / 2;
    if (NN > NMAX) NN = NMAX;
    if (EE > EMAX) EE = EMAX;

    k_pre0<<<2048, 256>>>(x, ei, batch, W, NN, EE);
    int NB = (NN + 1023) / 1024;
    k_scan1<<<NB, 1024>>>(NN);
    k_scan2<<<1, 128>>>(NB);
    k_scan3<<<NB, 1024>>>(NN, EE);
    k_dscan<<<1, DEGB>>>();
    k_dscatter<<<(NN + 511) / 512, 512>>>(NN);
    k_bucket<<<2048, 256>>>(ei, EE, NN);

    dim3 gb(12, 32);
    int ggrid = (NN + 31) / 32;
    int gemm_grid = (NN + 63) / 64;

    for (int it = 0; it < NSTEPS; it++) {
        k_gather<0><<<ggrid, gb>>>(gamma, beta, NN);
        k_gather<1><<<ggrid, gb>>>(gamma, beta, NN);
        k_gemm<<<gemm_grid, 128>>>(b, NN);
        k_gather<2><<<ggrid, gb>>>(gamma, beta, NN);
    }

    k_tail<<<NGRAPH, 256>>>(W1, b1, W2, b2, (float*)d_out);
}

// round 12
// speedup vs baseline: 1.2922x; 1.2352x over previous
#include <cuda_runtime.h>
#include <cuda_bf16.h>
#include <cuda_fp16.h>
#include <stdint.h>

#define NMAX 100000
#define EMAX 1600000
#define D 48
#define D4 12
#define HSTRIDE 64   // halfs per row (48 used, padded to 128 B)
#define HS2 16       // uint2 per row
#define NSTEPS 5
#define NGRAPH 64
#define DEGB 512
#define BN_EPS 1e-5f
#define ASTR 148     // smem A stride (uints) for tf32 GEMM

// ---------------- device scratch ----------------
__device__ int   g_deg[NMAX];
__device__ float g_dinv[NMAX];
__device__ int   g_rowstart[NMAX + 1];
__device__ int   g_wp[NMAX];
__device__ int   g_ecol[EMAX];
__device__ int   g_scanblk[256];
__device__ int   g_scanoff[256];
__device__ int   g_dhist[DEGB];
__device__ int   g_doff[DEGB];
__device__ int   g_perm[NMAX];
__device__ unsigned g_Wt[144 * 48];                    // tf32-converted weights
__device__ __align__(16) float  g_X [NMAX * D];
__device__ __align__(16) float  g_T1[NMAX * D];
__device__ __align__(16) float  g_T2[NMAX * D];
__device__ __align__(16) __half g_Yh [NMAX * HSTRIDE];
__device__ __align__(16) __half g_Y2h[NMAX * HSTRIDE];
__device__ __align__(16) __half g_Th [NMAX * HSTRIDE];
__device__ double g_bnsum[D];
__device__ double g_bnsq[D];
__device__ float g_g[NGRAPH * D];
__device__ int   g_gstart[NGRAPH + 1];

// ---------------- helpers ----------------
__device__ __forceinline__ float4 f4add(float4 a, float4 b) {
    return make_float4(a.x + b.x, a.y + b.y, a.z + b.z, a.w + b.w);
}
__device__ __forceinline__ float4 f4max(float4 a, float4 b) {
    return make_float4(fmaxf(a.x, b.x), fmaxf(a.y, b.y), fmaxf(a.z, b.z),
                       fmaxf(a.w, b.w));
}
__device__ __forceinline__ float4 f4fma(float4 a, float4 v, float4 c) {
    return make_float4(fmaf(a.x, v.x, c.x), fmaf(a.y, v.y, c.y),
                       fmaf(a.z, v.z, c.z), fmaf(a.w, v.w, c.w));
}
__device__ __forceinline__ float4 f4scale(float s, float4 v) {
    return make_float4(s * v.x, s * v.y, s * v.z, s * v.w);
}
__device__ __forceinline__ float4 h4_to_f4(uint2 v) {
    __half2 h0 = *(__half2*)&v.x;
    __half2 h1 = *(__half2*)&v.y;
    float2 f0 = __half22float2(h0);
    float2 f1 = __half22float2(h1);
    return make_float4(f0.x, f0.y, f1.x, f1.y);
}
__device__ __forceinline__ uint2 f4_to_h4(float4 f) {
    __half2 h0 = __floats2half2_rn(f.x, f.y);
    __half2 h1 = __floats2half2_rn(f.z, f.w);
    uint2 r;
    r.x = *(unsigned*)&h0;
    r.y = *(unsigned*)&h1;
    return r;
}
__device__ __forceinline__ int idx_get(const void* p, int i, int is64) {
    return is64 ? (int)((const long long*)p)[i] : ((const int*)p)[i];
}
__device__ __forceinline__ int probe64(const void* p, int NN) {
    const long long* q = (const long long*)p;
    long long v0 = q[0], v1 = q[1], v2 = q[2], v3 = q[3];
    return (v0 >= 0 && v0 < NN && v1 >= 0 && v1 < NN && v2 >= 0 && v2 < NN &&
            v3 >= 0 && v3 < NN);
}
__device__ __forceinline__ unsigned f2tf32(float f) {
    unsigned u;
    asm("cvt.rna.tf32.f32 %0, %1;" : "=r"(u) : "f"(f));
    return u;
}

// ------- pre0: copy X, count deg, gstart, convert W, zero bnsums -----------
__global__ void k_pre0(const float* __restrict__ x, const void* ei,
                       const void* batch, const float* __restrict__ W, int NN,
                       int EE) {
    int gt = blockIdx.x * blockDim.x + threadIdx.x;
    int gs = gridDim.x * blockDim.x;
    int is64 = probe64(ei, NN);

    for (int i = gt; i < NN * D4; i += gs)
        ((float4*)g_X)[i] = ((const float4*)x)[i];
    for (int e = gt; e < EE; e += gs) {
        int r = idx_get(ei, e, is64);
        if ((unsigned)r < (unsigned)NN) atomicAdd(&g_deg[r], 1);
    }
    for (int i = gt; i <= NN; i += gs) {
        int bi = (i < NN) ? idx_get(batch, i, is64) : NGRAPH;
        int bp = (i > 0) ? idx_get(batch, i - 1, is64) : -1;
        if (bi < 0) bi = 0;
        if (bi > NGRAPH) bi = NGRAPH;
        if (bp < -1) bp = -1;
        if (bp > NGRAPH) bp = NGRAPH;
        for (int g = bp + 1; g <= bi; g++) g_gstart[g] = i;
    }
    for (int i = gt; i < 144 * 48; i += gs) g_Wt[i] = f2tf32(W[i]);
    if (gt < D) { g_bnsum[gt] = 0.0; g_bnsq[gt] = 0.0; }
}

// ---------------- prefix scan over deg (+dinv +degree histogram) -----------
__global__ void k_scan1(int NN) {
    __shared__ int sh[1024];
    __shared__ int hist[DEGB];
    int t = threadIdx.x;
    if (t < DEGB) hist[t] = 0;
    int i = blockIdx.x * 1024 + t;
    int v = (i < NN) ? g_deg[i] : 0;
    sh[t] = v;
    __syncthreads();
    for (int off = 1; off < 1024; off <<= 1) {
        int tv = (t >= off) ? sh[t - off] : 0;
        __syncthreads();
        sh[t] += tv;
        __syncthreads();
    }
    if (i < NN) {
        g_rowstart[i] = sh[t] - v;
        g_dinv[i] = (v > 0) ? rsqrtf((float)v) : 0.0f;
        atomicAdd(&hist[v < DEGB ? v : DEGB - 1], 1);
    }
    if (t == 1023) g_scanblk[blockIdx.x] = sh[1023];
    __syncthreads();
    if (t < DEGB && hist[t] > 0) atomicAdd(&g_dhist[t], hist[t]);
}

// scan2: block-offset scan (NB<=128) + degree-bucket scan (DEGB), one block.
__global__ void k_scan2(int NB) {
    __shared__ int sh[DEGB];
    int t = threadIdx.x;  // 512
    // part 1: scan of per-block totals
    if (t < 128) {
        int v = (t < NB) ? g_scanblk[t] : 0;
        sh[t] = v;
    }
    __syncthreads();
    if (t < 128) {
        int acc = sh[t];
        for (int off = 1; off < 128; off <<= 1) {
            int tv = (t >= off) ? sh[t - off] : 0;
            __syncthreads();
            sh[t] += tv;
            __syncthreads();
        }
        (void)acc;
        g_scanoff[t] = sh[t] - ((t < NB) ? g_scanblk[t] : 0);
    } else {
        for (int off = 1; off < 128; off <<= 1) {
            __syncthreads();
            __syncthreads();
        }
    }
    __syncthreads();
    // part 2: degree-bucket exclusive scan
    int v = g_dhist[t];
    sh[t] = v;
    __syncthreads();
    for (int off = 1; off < DEGB; off <<= 1) {
        int tv = (t >= off) ? sh[t - off] : 0;
        __syncthreads();
        sh[t] += tv;
        __syncthreads();
    }
    g_doff[t] = sh[t] - v;
    g_dhist[t] = 0;  // reset for next replay
}

// scan3 + prescale (Yh = half(dinv*X)) fused
__global__ void k_scan3(int NN, int EE) {
    int i = blockIdx.x * 1024 + threadIdx.x;
    if (i < NN) {
        int rs = g_rowstart[i] + g_scanoff[blockIdx.x];
        g_rowstart[i] = rs;
        g_wp[i] = rs;
    }
    if (i == 0) g_rowstart[NN] = EE;
    int gs = gridDim.x * 1024;
    for (int v = i; v < NN * D4; v += gs) {
        int row = v / D4, f = v % D4;
        float4 val = f4scale(g_dinv[row], ((const float4*)g_X)[v]);
        ((uint2*)g_Yh)[row * HS2 + f] = f4_to_h4(val);
    }
}

__global__ void k_dscatter(int NN) {
    __shared__ int lh[DEGB];
    __shared__ int lbase[DEGB];
    int t = threadIdx.x;
    lh[t] = 0;
    __syncthreads();
    int i = blockIdx.x * 512 + t;
    int d = 0, lr = 0;
    if (i < NN) {
        d = g_deg[i];
        if (d >= DEGB) d = DEGB - 1;
        lr = atomicAdd(&lh[d], 1);
        g_deg[i] = 0;
    }
    __syncthreads();
    if (lh[t] > 0) lbase[t] = atomicAdd(&g_doff[t], lh[t]);
    __syncthreads();
    if (i < NN) g_perm[lbase[d] + lr] = i;
}

__global__ void k_bucket(const void* __restrict__ ei, int EE, int NN) {
    int is64 = probe64(ei, NN);
    for (int e = blockIdx.x * blockDim.x + threadIdx.x; e < EE;
         e += gridDim.x * blockDim.x) {
        int r = idx_get(ei, e, is64);
        int c = idx_get(ei, EE + e, is64);
        if ((unsigned)r < (unsigned)NN && (unsigned)c < (unsigned)NN) {
            int p = atomicAdd(&g_wp[r], 1);
            if ((unsigned)p < (unsigned)EMAX) g_ecol[p] = c;
        }
    }
}

// ---------------- CSR gather kernels (12 lanes x uint2, unroll 4) ----------
// MODE 0: T1 = -dinv*sum(Yh[c]);  Y2h = dinv*T1;  block 0 zeroes BN sums
// MODE 1: T2 = -2*dinv*sum(Y2h[c]) - X
// MODE 2: inline BN-finalize, then X = deg>0 ? max_c(a*Th[c]+c) : 0; Yh=dinv*X
template <int MODE>
__global__ __launch_bounds__(384) void k_gather(const float* __restrict__ gamma,
                                                const float* __restrict__ beta,
                                                int NN) {
    __shared__ __align__(16) float sa[48], sc[48];
    int lt = threadIdx.y * 12 + threadIdx.x;
    if (MODE == 0) {
        if (blockIdx.x == 0 && lt < D) { g_bnsum[lt] = 0.0; g_bnsq[lt] = 0.0; }
    }
    if (MODE == 2) {
        if (lt < D) {
            double mean = g_bnsum[lt] / (double)NN;
            double var = g_bnsq[lt] / (double)NN - mean * mean;
            float a = gamma[lt] * rsqrtf((float)var + BN_EPS);
            sa[lt] = a;
            sc[lt] = beta[lt] - (float)mean * a;
        }
        __syncthreads();
    }
    int vrow = blockIdx.x * 32 + threadIdx.y;
    if (vrow >= NN) return;
    int row = g_perm[vrow];
    int f = threadIdx.x;  // 0..11
    int s = g_rowstart[row];
    int e = g_rowstart[row + 1];
    const uint2* __restrict__ src =
        (MODE == 0) ? (const uint2*)g_Yh
                    : (MODE == 1) ? (const uint2*)g_Y2h : (const uint2*)g_Th;
    const int* __restrict__ ec = g_ecol;

    if (MODE == 2) {
        float4 av = ((const float4*)sa)[f];
        float4 cv = ((const float4*)sc)[f];
        float NI = __int_as_float(0xff800000);
        float4 m0 = make_float4(NI, NI, NI, NI), m1 = m0, m2 = m0, m3 = m0;
        int i = s;
        for (; i + 4 <= e; i += 4) {
            int c0 = __ldg(ec + i), c1 = __ldg(ec + i + 1);
            int c2 = __ldg(ec + i + 2), c3 = __ldg(ec + i + 3);
            float4 v0 = h4_to_f4(__ldg(src + c0 * HS2 + f));
            float4 v1 = h4_to_f4(__ldg(src + c1 * HS2 + f));
            float4 v2 = h4_to_f4(__ldg(src + c2 * HS2 + f));
            float4 v3 = h4_to_f4(__ldg(src + c3 * HS2 + f));
            m0 = f4max(m0, f4fma(av, v0, cv));
            m1 = f4max(m1, f4fma(av, v1, cv));
            m2 = f4max(m2, f4fma(av, v2, cv));
            m3 = f4max(m3, f4fma(av, v3, cv));
        }
        for (; i < e; i++) {
            int c = __ldg(ec + i);
            m0 = f4max(m0, f4fma(av, h4_to_f4(__ldg(src + c * HS2 + f)), cv));
        }
        float4 m = f4max(f4max(m0, m1), f4max(m2, m3));
        float4 xv = (e > s) ? m : make_float4(0.f, 0.f, 0.f, 0.f);
        ((float4*)g_X)[row * D4 + f] = xv;
        ((uint2*)g_Yh)[row * HS2 + f] = f4_to_h4(f4scale(g_dinv[row], xv));
    } else {
        float4 a0 = make_float4(0.f, 0.f, 0.f, 0.f), a1 = a0, a2 = a0, a3 = a0;
        int i = s;
        for (; i + 4 <= e; i += 4) {
            int c0 = __ldg(ec + i), c1 = __ldg(ec + i + 1);
            int c2 = __ldg(ec + i + 2), c3 = __ldg(ec + i + 3);
            a0 = f4add(a0, h4_to_f4(__ldg(src + c0 * HS2 + f)));
            a1 = f4add(a1, h4_to_f4(__ldg(src + c1 * HS2 + f)));
            a2 = f4add(a2, h4_to_f4(__ldg(src + c2 * HS2 + f)));
            a3 = f4add(a3, h4_to_f4(__ldg(src + c3 * HS2 + f)));
        }
        for (; i < e; i++) {
            int c = __ldg(ec + i);
            a0 = f4add(a0, h4_to_f4(__ldg(src + c * HS2 + f)));
        }
        float4 sum = f4add(f4add(a0, a1), f4add(a2, a3));
        float dr = g_dinv[row];
        if (MODE == 0) {
            float4 t1 = f4scale(-dr, sum);
            ((float4*)g_T1)[row * D4 + f] = t1;
            ((uint2*)g_Y2h)[row * HS2 + f] = f4_to_h4(f4scale(dr, t1));
        } else {
            float4 xr = __ldg((const float4*)g_X + row * D4 + f);
            float4 t2;
            float nd = -2.0f * dr;
            t2.x = fmaf(nd, sum.x, -xr.x);
            t2.y = fmaf(nd, sum.y, -xr.y);
            t2.z = fmaf(nd, sum.z, -xr.z);
            t2.w = fmaf(nd, sum.w, -xr.w);
            ((float4*)g_T2)[row * D4 + f] = t2;
        }
    }
}

// ------- tf32 tensor-core cheb GEMM + fused BN stats -----------------------
__global__ __launch_bounds__(128) void k_gemm(const float* __restrict__ b,
                                              int NN) {
    __shared__ unsigned As[64 * ASTR];
    __shared__ float bsumS[48], bsqS[48];
    int tid = threadIdx.x;
    int w = tid >> 5;
    int lane = tid & 31;
    int g = lane >> 2;
    int t = lane & 3;
    int nodebase = blockIdx.x * 64;

    if (tid < 48) { bsumS[tid] = 0.f; bsqS[tid] = 0.f; }

    for (int idx = tid; idx < 64 * 36; idx += 128) {
        int node = idx / 36, q = idx % 36;
        int buf = q / 12, c4 = q % 12;
        int gn = nodebase + node;
        float4 v = make_float4(0.f, 0.f, 0.f, 0.f);
        if (gn < NN) {
            const float* sp = (buf == 0) ? g_X : (buf == 1) ? g_T1 : g_T2;
            v = ((const float4*)sp)[gn * D4 + c4];
        }
        int k = buf * 48 + c4 * 4;
        unsigned* dst = &As[node * ASTR + k];
        dst[0] = f2tf32(v.x);
        dst[1] = f2tf32(v.y);
        dst[2] = f2tf32(v.z);
        dst[3] = f2tf32(v.w);
    }
    __syncthreads();

    float acc[6][4];
#pragma unroll
    for (int j = 0; j < 6; j++)
#pragma unroll
        for (int q = 0; q < 4; q++) acc[j][q] = 0.f;

    const unsigned* __restrict__ Wt = g_Wt;
    int r0s = (w * 16 + g) * ASTR;
    int r1s = (w * 16 + g + 8) * ASTR;
#pragma unroll
    for (int s = 0; s < 18; s++) {
        int k0 = s * 8;
        unsigned a0 = As[r0s + k0 + t];
        unsigned a1 = As[r1s + k0 + t];
        unsigned a2 = As[r0s + k0 + t + 4];
        unsigned a3 = As[r1s + k0 + t + 4];
#pragma unroll
        for (int j = 0; j < 6; j++) {
            unsigned b0 = __ldg(&Wt[(k0 + t) * 48 + j * 8 + g]);
            unsigned b1 = __ldg(&Wt[(k0 + t + 4) * 48 + j * 8 + g]);
            asm volatile(
                "mma.sync.aligned.m16n8k8.row.col.f32.tf32.tf32.f32 "
                "{%0,%1,%2,%3}, {%4,%5,%6,%7}, {%8,%9}, {%0,%1,%2,%3};"
                : "+f"(acc[j][0]), "+f"(acc[j][1]), "+f"(acc[j][2]),
                  "+f"(acc[j][3])
                : "r"(a0), "r"(a1), "r"(a2), "r"(a3), "r"(b0), "r"(b1));
        }
    }

    int r0 = nodebase + w * 16 + g;
    int r1 = r0 + 8;
    bool v0 = r0 < NN, v1 = r1 < NN;
#pragma unroll
    for (int j = 0; j < 6; j++) {
        int col0 = j * 8 + 2 * t;
        float bb0 = __ldg(b + col0);
        float bb1 = __ldg(b + col0 + 1);
        float o00 = fmaxf(acc[j][0] + bb0, 0.f);
        float o01 = fmaxf(acc[j][1] + bb1, 0.f);
        float o10 = fmaxf(acc[j][2] + bb0, 0.f);
        float o11 = fmaxf(acc[j][3] + bb1, 0.f);
        if (v0) {
            __half2 h = __floats2half2_rn(o00, o01);
            ((unsigned*)g_Th)[r0 * 32 + j * 4 + t] = *(unsigned*)&h;
        }
        if (v1) {
            __half2 h = __floats2half2_rn(o10, o11);
            ((unsigned*)g_Th)[r1 * 32 + j * 4 + t] = *(unsigned*)&h;
        }
        float s0 = (v0 ? o00 : 0.f) + (v1 ? o10 : 0.f);
        float s1 = (v0 ? o01 : 0.f) + (v1 ? o11 : 0.f);
        float q0 = (v0 ? o00 * o00 : 0.f) + (v1 ? o10 * o10 : 0.f);
        float q1 = (v0 ? o01 * o01 : 0.f) + (v1 ? o11 * o11 : 0.f);
#pragma unroll
        for (int m = 4; m < 32; m <<= 1) {
            s0 += __shfl_xor_sync(0xffffffffu, s0, m);
            s1 += __shfl_xor_sync(0xffffffffu, s1, m);
            q0 += __shfl_xor_sync(0xffffffffu, q0, m);
            q1 += __shfl_xor_sync(0xffffffffu, q1, m);
        }
        if (g == 0) {
            atomicAdd(&bsumS[col0], s0);
            atomicAdd(&bsumS[col0 + 1], s1);
            atomicAdd(&bsqS[col0], q0);
            atomicAdd(&bsqS[col0 + 1], q1);
        }
    }
    __syncthreads();
    if (tid < 48) {
        atomicAdd(&g_bnsum[tid], (double)bsumS[tid]);
        atomicAdd(&g_bnsq[tid], (double)bsqS[tid]);
    }
}

// ---------------- tail: global add pool + MLP, one block per graph ----------
__global__ __launch_bounds__(256) void k_tail(const float* __restrict__ W1,
                                              const float* __restrict__ b1,
                                              const float* __restrict__ W2,
                                              const float* __restrict__ b2,
                                              float* __restrict__ out) {
    __shared__ float sh[5 * D];
    __shared__ float gr[D];
    __shared__ float hs[128];
    int gph = blockIdx.x;
    int t = threadIdx.x;
    int st = g_gstart[gph], en = g_gstart[gph + 1];
    if (t < 240) {
        int f = t % D;
        int s = t / D;
        float acc = 0.0f;
        for (int n = st + s; n < en; n += 5) acc += g_X[n * D + f];
        sh[s * D + f] = acc;
    }
    __syncthreads();
    if (t < D)
        gr[t] = sh[t] + sh[D + t] + sh[2 * D + t] + sh[3 * D + t] + sh[4 * D + t];
    __syncthreads();
    if (t < 128) {
        float a = b1[t];
#pragma unroll
        for (int k = 0; k < D; k++) a = fmaf(gr[k], W1[k * 128 + t], a);
        hs[t] = fmaxf(a, 0.0f);
    }
    __syncthreads();
    if (t < 12) {
        float o = b2[t];
#pragma unroll
        for (int j = 0; j < 128; j++) o = fmaf(hs[j], W2[j * 12 + t], o);
        out[gph * 12 + t] = o;
    }
}

// ---------------- host orchestration ----------------
extern "C" void kernel_launch(void* const* d_in, const int* in_sizes, int n_in,
                              void* d_out, int out_size) {
    const float* x    = (const float*)d_in[0];
    const void* ei    = d_in[1];
    const void* batch = d_in[2];
    int base = 3;
    if (n_in >= 12 && in_sizes[3] < 100) base = 4;
    const float* W     = (const float*)d_in[base + 0];
    const float* b     = (const float*)d_in[base + 1];
    const float* gamma = (const float*)d_in[base + 2];
    const float* beta  = (const float*)d_in[base + 3];
    const float* W1    = (const float*)d_in[base + 4];
    const float* b1    = (const float*)d_in[base + 5];
    const float* W2    = (const float*)d_in[base + 6];
    const float* b2    = (const float*)d_in[base + 7];

    int NN = in_sizes[0] / D;
    int EE = in_sizes[1] / 2;
    if (NN > NMAX) NN = NMAX;
    if (EE > EMAX) EE = EMAX;

    k_pre0<<<2048, 256>>>(x, ei, batch, W, NN, EE);
    int NB = (NN + 1023) / 1024;
    k_scan1<<<NB, 1024>>>(NN);
    k_scan2<<<1, DEGB>>>(NB);                  // block-offset + degree scans
    k_scan3<<<NB, 1024>>>(NN, EE);
    k_dscatter<<<(NN + 511) / 512, 512>>>(NN);
    k_bucket<<<2048, 256>>>(ei, EE, NN);

    dim3 gb(12, 32);
    int ggrid = (NN + 31) / 32;
    int gemm_grid = (NN + 63) / 64;

    for (int it = 0; it < NSTEPS; it++) {
        k_gather<0><<<ggrid, gb>>>(gamma, beta, NN);
        k_gather<1><<<ggrid, gb>>>(gamma, beta, NN);
        k_gemm<<<gemm_grid, 128>>>(b, NN);
        k_gather<2><<<ggrid, gb>>>(gamma, beta, NN);
    }

    k_tail<<<NGRAPH, 256>>>(W1, b1, W2, b2, (float*)d_out);
}